// round 8
// baseline (speedup 1.0000x reference)
#include <cuda_runtime.h>
#include <math.h>

#define MAX_N   100000
#define MAX_E   3200000
#define HID     32
#define IN_DIM  11
#define SCAN_BLK 256

// ---------------------------------------------------------------------------
// Static scratch (no allocation allowed).
// INVARIANT: g_deg is all-zero at kernel_launch entry (zero at static init;
// agg2_kernel resets it at the end of every call).
__device__ int   g_deg   [MAX_N];
__device__ float g_dinv  [MAX_N];
__device__ int   g_rowloc[MAX_N];
__device__ int   g_bsum  [1024];
__device__ int   g_boff  [1024];
__device__ int   g_row   [MAX_N];
__device__ int   g_cur   [MAX_N];
__device__ int   g_col   [MAX_E];
__device__ float g_y     [MAX_N * HID];
__device__ float g_y2    [MAX_N * HID];

// ---------------------------------------------------------------------------
// 1) degree histogram over dst (4 edges per thread, int4 loads)
__global__ void degree_kernel(const int* __restrict__ dst, int E) {
    int t = blockIdx.x * blockDim.x + threadIdx.x;
    int e = t * 4;
    if (e + 3 < E) {
        int4 d = __ldg(reinterpret_cast<const int4*>(dst) + t);
        atomicAdd(&g_deg[d.x], 1);
        atomicAdd(&g_deg[d.y], 1);
        atomicAdd(&g_deg[d.z], 1);
        atomicAdd(&g_deg[d.w], 1);
    } else {
        for (int k = e; k < E; k++) atomicAdd(&g_deg[dst[k]], 1);
    }
}

// 2a) per-block inclusive scan of degrees -> local exclusive + block sums
__global__ void scan1_kernel(int n) {
    __shared__ int s[SCAN_BLK];
    int tid = threadIdx.x;
    int i = blockIdx.x * SCAN_BLK + tid;
    int v = (i < n) ? g_deg[i] : 0;
    s[tid] = v; __syncthreads();
#pragma unroll
    for (int off = 1; off < SCAN_BLK; off <<= 1) {
        int t = (tid >= off) ? s[tid - off] : 0;
        __syncthreads();
        s[tid] += t;
        __syncthreads();
    }
    if (i < n) g_rowloc[i] = s[tid] - v;
    if (tid == SCAN_BLK - 1) g_bsum[blockIdx.x] = s[tid];
}

// 2b) single-block exclusive scan of block sums (nblk <= 1024)
__global__ void scan2_kernel(int nblk) {
    __shared__ int s[1024];
    int tid = threadIdx.x;
    int v = (tid < nblk) ? g_bsum[tid] : 0;
    s[tid] = v; __syncthreads();
#pragma unroll
    for (int off = 1; off < 1024; off <<= 1) {
        int t = (tid >= off) ? s[tid - off] : 0;
        __syncthreads();
        s[tid] += t;
        __syncthreads();
    }
    if (tid < nblk) g_boff[tid] = s[tid] - v;
}

// 3) y1 = dinv * (x @ W1); finalize row/cursor/dinv. 4 nodes per warp.
__global__ void y1_kernel(const float* __restrict__ x,
                          const float* __restrict__ W1, int n) {
    __shared__ float sW[IN_DIM * HID];
    for (int i = threadIdx.x; i < IN_DIM * HID; i += blockDim.x) sW[i] = W1[i];
    __syncthreads();

    int warp = threadIdx.x >> 5, lane = threadIdx.x & 31;
    int node0 = (blockIdx.x * (blockDim.x >> 5) + warp) * 4;
    if (node0 >= n) return;

    int base = node0 * IN_DIM;
    int lim = n * IN_DIM;
    float a = (base + lane < lim) ? x[base + lane] : 0.f;
    float b = (lane < 12 && base + 32 + lane < lim) ? x[base + 32 + lane] : 0.f;

#pragma unroll
    for (int j = 0; j < 4; j++) {
        int node = node0 + j;
        if (node >= n) break;
        float acc = 0.f;
#pragma unroll
        for (int k = 0; k < IN_DIM; k++) {
            int flat = j * IN_DIM + k;
            float xk = (flat < 32) ? __shfl_sync(0xffffffffu, a, flat)
                                   : __shfl_sync(0xffffffffu, b, flat - 32);
            acc = fmaf(xk, sW[k * HID + lane], acc);
        }
        float dv = rsqrtf((float)(g_deg[node] + 1));
        if (lane == 0) {
            g_dinv[node] = dv;
            int r = g_rowloc[node] + g_boff[node / SCAN_BLK];
            g_row[node] = r;
            g_cur[node] = r;
        }
        g_y[node * HID + lane] = dv * acc;
    }
}

// 4) fill CSR (4 edges per thread, int4 loads)
__global__ void fill_kernel(const int* __restrict__ src,
                            const int* __restrict__ dst, int E) {
    int t = blockIdx.x * blockDim.x + threadIdx.x;
    int e = t * 4;
    if (e + 3 < E) {
        int4 d = __ldg(reinterpret_cast<const int4*>(dst) + t);
        int4 s = __ldg(reinterpret_cast<const int4*>(src) + t);
        g_col[atomicAdd(&g_cur[d.x], 1)] = s.x;
        g_col[atomicAdd(&g_cur[d.y], 1)] = s.y;
        g_col[atomicAdd(&g_cur[d.z], 1)] = s.z;
        g_col[atomicAdd(&g_cur[d.w], 1)] = s.w;
    } else {
        for (int k = e; k < E; k++)
            g_col[atomicAdd(&g_cur[dst[k]], 1)] = src[k];
    }
}

// ---------------------------------------------------------------------------
// Gather: warp-per-node, float4 per lane, 4 edge rows per LDG.128 instruction,
// 16 edges per batch with double-buffered index loads. Returns per-lane scalar
// h_pre = sum over incoming rows + self row, for channel c = lane.
__device__ __forceinline__ float gather_row(const float* __restrict__ ybuf,
                                            int node, int lane) {
    int beg = g_row[node];
    int cnt = g_deg[node];
    int g   = lane & 7;       // float4 group within row
    int sub = lane >> 3;      // which edge of the quad this lane handles

    float4 acc = make_float4(0.f, 0.f, 0.f, 0.f);

    int i = 0;
    int idx = (cnt >= 16 && lane < 16) ? __ldg(&g_col[beg + lane]) : 0;
    for (; i + 16 <= cnt; i += 16) {
        int nidx = (i + 32 <= cnt && lane < 16)
                 ? __ldg(&g_col[beg + i + 16 + lane]) : 0;
#pragma unroll
        for (int it = 0; it < 4; it++) {
            int s = __shfl_sync(0xffffffffu, idx, it * 4 + sub);
            float4 v = __ldcg(reinterpret_cast<const float4*>(ybuf + s * HID) + g);
            acc.x += v.x; acc.y += v.y; acc.z += v.z; acc.w += v.w;
        }
        idx = nidx;
    }

    int rem = cnt - i;
    if (rem > 0) {
        int tidx = (lane < rem) ? __ldg(&g_col[beg + i + lane]) : 0;
        for (int it = 0; it * 4 < rem; it++) {
            int e = it * 4 + sub;
            int s = __shfl_sync(0xffffffffu, tidx, e & 15);
            if (e < rem) {
                float4 v = __ldcg(reinterpret_cast<const float4*>(ybuf + s * HID) + g);
                acc.x += v.x; acc.y += v.y; acc.z += v.z; acc.w += v.w;
            }
        }
    }

    // reduce across the 4 edge-subgroups (lanes differing in bits 3,4)
#pragma unroll
    for (int m = 8; m <= 16; m <<= 1) {
        acc.x += __shfl_xor_sync(0xffffffffu, acc.x, m);
        acc.y += __shfl_xor_sync(0xffffffffu, acc.y, m);
        acc.z += __shfl_xor_sync(0xffffffffu, acc.z, m);
        acc.w += __shfl_xor_sync(0xffffffffu, acc.w, m);
    }

    // transpose: channel c = lane lives in component (lane&3) of group (lane>>2)
    int gsrc = lane >> 2;
    float cx = __shfl_sync(0xffffffffu, acc.x, gsrc);
    float cy = __shfl_sync(0xffffffffu, acc.y, gsrc);
    float cz = __shfl_sync(0xffffffffu, acc.z, gsrc);
    float cw = __shfl_sync(0xffffffffu, acc.w, gsrc);
    int sel = lane & 3;
    float v = (sel == 0) ? cx : (sel == 1) ? cy : (sel == 2) ? cz : cw;

    // self-loop term (coalesced 128B load)
    return v + ybuf[node * HID + lane];
}

// 5) layer-1 aggregation + relu + W2 transform: y2 = dinv*(relu(dinv*sum+b1) @ W2)
__global__ void agg1_kernel(const float* __restrict__ b1,
                            const float* __restrict__ W2, int n) {
    __shared__ float sW[HID * HID];
    for (int i = threadIdx.x; i < HID * HID; i += blockDim.x) sW[i] = W2[i];
    __syncthreads();

    int warp = threadIdx.x >> 5, lane = threadIdx.x & 31;
    int node = blockIdx.x * (blockDim.x >> 5) + warp;
    if (node >= n) return;

    float acc = gather_row(g_y, node, lane);
    float dv  = g_dinv[node];
    float h   = fmaxf(fmaf(dv, acc, b1[lane]), 0.f);

    float o = 0.f;
#pragma unroll
    for (int k = 0; k < HID; k++) {
        float hk = __shfl_sync(0xffffffffu, h, k);
        o = fmaf(hk, sW[k * HID + lane], o);
    }
    g_y2[node * HID + lane] = dv * o;
}

// 6) layer-2 aggregation + relu + MLP head. Resets g_deg (invariant).
__global__ void agg2_kernel(const float* __restrict__ b2,
                            const float* __restrict__ Wo1,
                            const float* __restrict__ bo1,
                            const float* __restrict__ Wo2,
                            const float* __restrict__ bo2,
                            float* __restrict__ out, int n) {
    __shared__ float sW[HID * 16];
    __shared__ float sW2[16];
    for (int i = threadIdx.x; i < HID * 16; i += blockDim.x) sW[i] = Wo1[i];
    if (threadIdx.x < 16) sW2[threadIdx.x] = Wo2[threadIdx.x];
    __syncthreads();

    int warp = threadIdx.x >> 5, lane = threadIdx.x & 31;
    int node = blockIdx.x * (blockDim.x >> 5) + warp;
    if (node >= n) return;

    float acc = gather_row(g_y2, node, lane);
    float dv  = g_dinv[node];
    float h   = fmaxf(fmaf(dv, acc, b2[lane]), 0.f);

    int j = lane & 15;
    float t = 0.f;
#pragma unroll
    for (int k = 0; k < HID; k++) {
        float hk = __shfl_sync(0xffffffffu, h, k);
        t = fmaf(hk, sW[k * 16 + j], t);
    }
    t += bo1[j];
    t = (t > 0.f) ? t : expm1f(t);          // elu
    float p = (lane < 16) ? t * sW2[j] : 0.f;
    p += __shfl_down_sync(0xffffffffu, p, 8);
    p += __shfl_down_sync(0xffffffffu, p, 4);
    p += __shfl_down_sync(0xffffffffu, p, 2);
    p += __shfl_down_sync(0xffffffffu, p, 1);
    if (lane == 0) {
        out[node] = p + bo2[0];
        g_deg[node] = 0;                    // restore invariant for next call
    }
}

// ---------------------------------------------------------------------------
extern "C" void kernel_launch(void* const* d_in, const int* in_sizes, int n_in,
                              void* d_out, int out_size) {
    const float* x   = (const float*)d_in[0];
    const int*   ei  = (const int*)  d_in[1];   // [2, E] row-major
    const float* W1  = (const float*)d_in[3];
    const float* b1  = (const float*)d_in[4];
    const float* W2  = (const float*)d_in[5];
    const float* b2  = (const float*)d_in[6];
    const float* Wo1 = (const float*)d_in[7];
    const float* bo1 = (const float*)d_in[8];
    const float* Wo2 = (const float*)d_in[9];
    const float* bo2 = (const float*)d_in[10];
    float* out = (float*)d_out;

    int n = in_sizes[0] / IN_DIM;
    int E = in_sizes[1] / 2;
    const int* src = ei;
    const int* dst = ei + E;

    const int TPB = 256;
    int node_grid = (n + (TPB / 32) - 1) / (TPB / 32);          // warp per node
    int quad_grid = (n + (TPB / 32) * 4 - 1) / ((TPB / 32) * 4); // 4 nodes/warp
    int nblk = (n + SCAN_BLK - 1) / SCAN_BLK;
    int e4_grid = ((E + 3) / 4 + TPB - 1) / TPB;

    degree_kernel<<<e4_grid, TPB>>>(dst, E);
    scan1_kernel<<<nblk, SCAN_BLK>>>(n);
    scan2_kernel<<<1, 1024>>>(nblk);
    y1_kernel<<<quad_grid, TPB>>>(x, W1, n);
    fill_kernel<<<e4_grid, TPB>>>(src, dst, E);
    agg1_kernel<<<node_grid, TPB>>>(b1, W2, n);
    agg2_kernel<<<node_grid, TPB>>>(b2, Wo1, bo1, Wo2, bo2, out, n);
}

// round 9
// speedup vs baseline: 1.0020x; 1.0020x over previous
#include <cuda_runtime.h>
#include <math.h>

#define MAX_N   100000
#define MAX_E   3200000
#define HID     32
#define IN_DIM  11
#define SCAN_BLK 256

// ---------------------------------------------------------------------------
// Static scratch (no allocation allowed).
// INVARIANT: g_deg is all-zero at kernel_launch entry (zero at static init;
// agg2_kernel resets it at the end of every call).
__device__ int   g_deg   [MAX_N];
__device__ float g_dinv  [MAX_N];
__device__ int   g_rowloc[MAX_N];
__device__ int   g_bsum  [1024];
__device__ int   g_boff  [1024];
__device__ int   g_row   [MAX_N];
__device__ int   g_cur   [MAX_N];
__device__ int   g_col   [MAX_E];
__device__ float g_y     [MAX_N * HID];
__device__ float g_y2    [MAX_N * HID];

// ---------------------------------------------------------------------------
// 1) degree histogram over dst (4 edges per thread, int4 loads)
__global__ void degree_kernel(const int* __restrict__ dst, int E) {
    int t = blockIdx.x * blockDim.x + threadIdx.x;
    int e = t * 4;
    if (e + 3 < E) {
        int4 d = __ldg(reinterpret_cast<const int4*>(dst) + t);
        atomicAdd(&g_deg[d.x], 1);
        atomicAdd(&g_deg[d.y], 1);
        atomicAdd(&g_deg[d.z], 1);
        atomicAdd(&g_deg[d.w], 1);
    } else {
        for (int k = e; k < E; k++) atomicAdd(&g_deg[dst[k]], 1);
    }
}

// 2a) per-block inclusive scan of degrees -> local exclusive + block sums
__global__ void scan1_kernel(int n) {
    __shared__ int s[SCAN_BLK];
    int tid = threadIdx.x;
    int i = blockIdx.x * SCAN_BLK + tid;
    int v = (i < n) ? g_deg[i] : 0;
    s[tid] = v; __syncthreads();
#pragma unroll
    for (int off = 1; off < SCAN_BLK; off <<= 1) {
        int t = (tid >= off) ? s[tid - off] : 0;
        __syncthreads();
        s[tid] += t;
        __syncthreads();
    }
    if (i < n) g_rowloc[i] = s[tid] - v;
    if (tid == SCAN_BLK - 1) g_bsum[blockIdx.x] = s[tid];
}

// 2b) single-block exclusive scan of block sums (nblk <= 1024)
__global__ void scan2_kernel(int nblk) {
    __shared__ int s[1024];
    int tid = threadIdx.x;
    int v = (tid < nblk) ? g_bsum[tid] : 0;
    s[tid] = v; __syncthreads();
#pragma unroll
    for (int off = 1; off < 1024; off <<= 1) {
        int t = (tid >= off) ? s[tid - off] : 0;
        __syncthreads();
        s[tid] += t;
        __syncthreads();
    }
    if (tid < nblk) g_boff[tid] = s[tid] - v;
}

// 3) y1 = dinv * (x @ W1); finalize row/cursor/dinv. 4 nodes per warp.
__global__ void y1_kernel(const float* __restrict__ x,
                          const float* __restrict__ W1, int n) {
    __shared__ float sW[IN_DIM * HID];
    for (int i = threadIdx.x; i < IN_DIM * HID; i += blockDim.x) sW[i] = W1[i];
    __syncthreads();

    int warp = threadIdx.x >> 5, lane = threadIdx.x & 31;
    int node0 = (blockIdx.x * (blockDim.x >> 5) + warp) * 4;
    if (node0 >= n) return;

    int base = node0 * IN_DIM;
    int lim = n * IN_DIM;
    float a = (base + lane < lim) ? x[base + lane] : 0.f;
    float b = (lane < 12 && base + 32 + lane < lim) ? x[base + 32 + lane] : 0.f;

#pragma unroll
    for (int j = 0; j < 4; j++) {
        int node = node0 + j;
        if (node >= n) break;
        float acc = 0.f;
#pragma unroll
        for (int k = 0; k < IN_DIM; k++) {
            int flat = j * IN_DIM + k;
            float xk = (flat < 32) ? __shfl_sync(0xffffffffu, a, flat)
                                   : __shfl_sync(0xffffffffu, b, flat - 32);
            acc = fmaf(xk, sW[k * HID + lane], acc);
        }
        float dv = rsqrtf((float)(g_deg[node] + 1));
        if (lane == 0) {
            g_dinv[node] = dv;
            int r = g_rowloc[node] + g_boff[node / SCAN_BLK];
            g_row[node] = r;
            g_cur[node] = r;
        }
        g_y[node * HID + lane] = dv * acc;
    }
}

// 4) fill CSR (4 edges per thread, int4 loads)
__global__ void fill_kernel(const int* __restrict__ src,
                            const int* __restrict__ dst, int E) {
    int t = blockIdx.x * blockDim.x + threadIdx.x;
    int e = t * 4;
    if (e + 3 < E) {
        int4 d = __ldg(reinterpret_cast<const int4*>(dst) + t);
        int4 s = __ldg(reinterpret_cast<const int4*>(src) + t);
        g_col[atomicAdd(&g_cur[d.x], 1)] = s.x;
        g_col[atomicAdd(&g_cur[d.y], 1)] = s.y;
        g_col[atomicAdd(&g_cur[d.z], 1)] = s.z;
        g_col[atomicAdd(&g_cur[d.w], 1)] = s.w;
    } else {
        for (int k = e; k < E; k++)
            g_col[atomicAdd(&g_cur[dst[k]], 1)] = src[k];
    }
}

// ---------------------------------------------------------------------------
// Gather: warp-per-node, float4 per lane, 4 edge rows per LDG.128 instruction,
// 16 edges per batch with double-buffered index loads. Returns per-lane scalar
// h_pre = sum over incoming rows + self row, for channel c = lane.
__device__ __forceinline__ float gather_row(const float* __restrict__ ybuf,
                                            int node, int lane) {
    int beg = g_row[node];
    int cnt = g_deg[node];
    int g   = lane & 7;       // float4 group within row
    int sub = lane >> 3;      // which edge of the quad this lane handles

    float4 acc = make_float4(0.f, 0.f, 0.f, 0.f);

    int i = 0;
    int idx = (cnt >= 16 && lane < 16) ? __ldg(&g_col[beg + lane]) : 0;
    for (; i + 16 <= cnt; i += 16) {
        int nidx = (i + 32 <= cnt && lane < 16)
                 ? __ldg(&g_col[beg + i + 16 + lane]) : 0;
#pragma unroll
        for (int it = 0; it < 4; it++) {
            int s = __shfl_sync(0xffffffffu, idx, it * 4 + sub);
            float4 v = __ldcg(reinterpret_cast<const float4*>(ybuf + s * HID) + g);
            acc.x += v.x; acc.y += v.y; acc.z += v.z; acc.w += v.w;
        }
        idx = nidx;
    }

    int rem = cnt - i;
    if (rem > 0) {
        int tidx = (lane < rem) ? __ldg(&g_col[beg + i + lane]) : 0;
        for (int it = 0; it * 4 < rem; it++) {
            int e = it * 4 + sub;
            int s = __shfl_sync(0xffffffffu, tidx, e & 15);
            if (e < rem) {
                float4 v = __ldcg(reinterpret_cast<const float4*>(ybuf + s * HID) + g);
                acc.x += v.x; acc.y += v.y; acc.z += v.z; acc.w += v.w;
            }
        }
    }

    // reduce across the 4 edge-subgroups (lanes differing in bits 3,4)
#pragma unroll
    for (int m = 8; m <= 16; m <<= 1) {
        acc.x += __shfl_xor_sync(0xffffffffu, acc.x, m);
        acc.y += __shfl_xor_sync(0xffffffffu, acc.y, m);
        acc.z += __shfl_xor_sync(0xffffffffu, acc.z, m);
        acc.w += __shfl_xor_sync(0xffffffffu, acc.w, m);
    }

    // transpose: channel c = lane lives in component (lane&3) of group (lane>>2)
    int gsrc = lane >> 2;
    float cx = __shfl_sync(0xffffffffu, acc.x, gsrc);
    float cy = __shfl_sync(0xffffffffu, acc.y, gsrc);
    float cz = __shfl_sync(0xffffffffu, acc.z, gsrc);
    float cw = __shfl_sync(0xffffffffu, acc.w, gsrc);
    int sel = lane & 3;
    float v = (sel == 0) ? cx : (sel == 1) ? cy : (sel == 2) ? cz : cw;

    // self-loop term (coalesced 128B load)
    return v + ybuf[node * HID + lane];
}

// 5) layer-1 aggregation + relu + W2 transform: y2 = dinv*(relu(dinv*sum+b1) @ W2)
__global__ void agg1_kernel(const float* __restrict__ b1,
                            const float* __restrict__ W2, int n) {
    __shared__ float sW[HID * HID];
    for (int i = threadIdx.x; i < HID * HID; i += blockDim.x) sW[i] = W2[i];
    __syncthreads();

    int warp = threadIdx.x >> 5, lane = threadIdx.x & 31;
    int node = blockIdx.x * (blockDim.x >> 5) + warp;
    if (node >= n) return;

    float acc = gather_row(g_y, node, lane);
    float dv  = g_dinv[node];
    float h   = fmaxf(fmaf(dv, acc, b1[lane]), 0.f);

    float o = 0.f;
#pragma unroll
    for (int k = 0; k < HID; k++) {
        float hk = __shfl_sync(0xffffffffu, h, k);
        o = fmaf(hk, sW[k * HID + lane], o);
    }
    g_y2[node * HID + lane] = dv * o;
}

// 6) layer-2 aggregation + relu + MLP head. Resets g_deg (invariant).
__global__ void agg2_kernel(const float* __restrict__ b2,
                            const float* __restrict__ Wo1,
                            const float* __restrict__ bo1,
                            const float* __restrict__ Wo2,
                            const float* __restrict__ bo2,
                            float* __restrict__ out, int n) {
    __shared__ float sW[HID * 16];
    __shared__ float sW2[16];
    for (int i = threadIdx.x; i < HID * 16; i += blockDim.x) sW[i] = Wo1[i];
    if (threadIdx.x < 16) sW2[threadIdx.x] = Wo2[threadIdx.x];
    __syncthreads();

    int warp = threadIdx.x >> 5, lane = threadIdx.x & 31;
    int node = blockIdx.x * (blockDim.x >> 5) + warp;
    if (node >= n) return;

    float acc = gather_row(g_y2, node, lane);
    float dv  = g_dinv[node];
    float h   = fmaxf(fmaf(dv, acc, b2[lane]), 0.f);

    int j = lane & 15;
    float t = 0.f;
#pragma unroll
    for (int k = 0; k < HID; k++) {
        float hk = __shfl_sync(0xffffffffu, h, k);
        t = fmaf(hk, sW[k * 16 + j], t);
    }
    t += bo1[j];
    t = (t > 0.f) ? t : expm1f(t);          // elu
    float p = (lane < 16) ? t * sW2[j] : 0.f;
    p += __shfl_down_sync(0xffffffffu, p, 8);
    p += __shfl_down_sync(0xffffffffu, p, 4);
    p += __shfl_down_sync(0xffffffffu, p, 2);
    p += __shfl_down_sync(0xffffffffu, p, 1);
    if (lane == 0) {
        out[node] = p + bo2[0];
        g_deg[node] = 0;                    // restore invariant for next call
    }
}

// ---------------------------------------------------------------------------
extern "C" void kernel_launch(void* const* d_in, const int* in_sizes, int n_in,
                              void* d_out, int out_size) {
    const float* x   = (const float*)d_in[0];
    const int*   ei  = (const int*)  d_in[1];   // [2, E] row-major
    const float* W1  = (const float*)d_in[3];
    const float* b1  = (const float*)d_in[4];
    const float* W2  = (const float*)d_in[5];
    const float* b2  = (const float*)d_in[6];
    const float* Wo1 = (const float*)d_in[7];
    const float* bo1 = (const float*)d_in[8];
    const float* Wo2 = (const float*)d_in[9];
    const float* bo2 = (const float*)d_in[10];
    float* out = (float*)d_out;

    int n = in_sizes[0] / IN_DIM;
    int E = in_sizes[1] / 2;
    const int* src = ei;
    const int* dst = ei + E;

    const int TPB = 256;
    int node_grid = (n + (TPB / 32) - 1) / (TPB / 32);          // warp per node
    int quad_grid = (n + (TPB / 32) * 4 - 1) / ((TPB / 32) * 4); // 4 nodes/warp
    int nblk = (n + SCAN_BLK - 1) / SCAN_BLK;
    int e4_grid = ((E + 3) / 4 + TPB - 1) / TPB;

    degree_kernel<<<e4_grid, TPB>>>(dst, E);
    scan1_kernel<<<nblk, SCAN_BLK>>>(n);
    scan2_kernel<<<1, 1024>>>(nblk);
    y1_kernel<<<quad_grid, TPB>>>(x, W1, n);
    fill_kernel<<<e4_grid, TPB>>>(src, dst, E);
    agg1_kernel<<<node_grid, TPB>>>(b1, W2, n);
    agg2_kernel<<<node_grid, TPB>>>(b2, Wo1, bo1, Wo2, bo2, out, n);
}

// round 12
// speedup vs baseline: 1.0028x; 1.0008x over previous
#include <cuda_runtime.h>
#include <math.h>

#define MAX_N   100000
#define MAX_E   3200000
#define HID     32
#define IN_DIM  11
#define SCAN_BLK 256

// ---------------------------------------------------------------------------
// Static scratch (no allocation allowed).
// INVARIANT: g_deg is all-zero at kernel_launch entry (zero at static init;
// agg2_kernel resets it at the end of every call).
__device__ int   g_deg   [MAX_N];
__device__ float g_dinv  [MAX_N];
__device__ int   g_rowloc[MAX_N];
__device__ int   g_bsum  [1024];
__device__ int   g_boff  [1024];
__device__ int   g_row   [MAX_N];
__device__ int   g_cur   [MAX_N];
__device__ int   g_col   [MAX_E];
__device__ float g_y     [MAX_N * HID];
__device__ float g_y2    [MAX_N * HID];

// ---------------------------------------------------------------------------
// 1) degree histogram over dst (4 edges per thread, int4 loads)
__global__ void degree_kernel(const int* __restrict__ dst, int E) {
    int t = blockIdx.x * blockDim.x + threadIdx.x;
    int e = t * 4;
    if (e + 3 < E) {
        int4 d = __ldg(reinterpret_cast<const int4*>(dst) + t);
        atomicAdd(&g_deg[d.x], 1);
        atomicAdd(&g_deg[d.y], 1);
        atomicAdd(&g_deg[d.z], 1);
        atomicAdd(&g_deg[d.w], 1);
    } else {
        for (int k = e; k < E; k++) atomicAdd(&g_deg[dst[k]], 1);
    }
}

// 2a) per-block inclusive scan of degrees -> local exclusive + block sums
__global__ void scan1_kernel(int n) {
    __shared__ int s[SCAN_BLK];
    int tid = threadIdx.x;
    int i = blockIdx.x * SCAN_BLK + tid;
    int v = (i < n) ? g_deg[i] : 0;
    s[tid] = v; __syncthreads();
#pragma unroll
    for (int off = 1; off < SCAN_BLK; off <<= 1) {
        int t = (tid >= off) ? s[tid - off] : 0;
        __syncthreads();
        s[tid] += t;
        __syncthreads();
    }
    if (i < n) g_rowloc[i] = s[tid] - v;
    if (tid == SCAN_BLK - 1) g_bsum[blockIdx.x] = s[tid];
}

// 2b) single-block exclusive scan of block sums (nblk <= 1024)
__global__ void scan2_kernel(int nblk) {
    __shared__ int s[1024];
    int tid = threadIdx.x;
    int v = (tid < nblk) ? g_bsum[tid] : 0;
    s[tid] = v; __syncthreads();
#pragma unroll
    for (int off = 1; off < 1024; off <<= 1) {
        int t = (tid >= off) ? s[tid - off] : 0;
        __syncthreads();
        s[tid] += t;
        __syncthreads();
    }
    if (tid < nblk) g_boff[tid] = s[tid] - v;
}

// 3) y1 = dinv * (x @ W1); finalize row/cursor/dinv. 4 nodes per warp.
__global__ void y1_kernel(const float* __restrict__ x,
                          const float* __restrict__ W1, int n) {
    __shared__ float sW[IN_DIM * HID];
    for (int i = threadIdx.x; i < IN_DIM * HID; i += blockDim.x) sW[i] = W1[i];
    __syncthreads();

    int warp = threadIdx.x >> 5, lane = threadIdx.x & 31;
    int node0 = (blockIdx.x * (blockDim.x >> 5) + warp) * 4;
    if (node0 >= n) return;

    int base = node0 * IN_DIM;
    int lim = n * IN_DIM;
    float a = (base + lane < lim) ? x[base + lane] : 0.f;
    float b = (lane < 12 && base + 32 + lane < lim) ? x[base + 32 + lane] : 0.f;

#pragma unroll
    for (int j = 0; j < 4; j++) {
        int node = node0 + j;
        if (node >= n) break;
        float acc = 0.f;
#pragma unroll
        for (int k = 0; k < IN_DIM; k++) {
            int flat = j * IN_DIM + k;
            float xk = (flat < 32) ? __shfl_sync(0xffffffffu, a, flat)
                                   : __shfl_sync(0xffffffffu, b, flat - 32);
            acc = fmaf(xk, sW[k * HID + lane], acc);
        }
        float dv = rsqrtf((float)(g_deg[node] + 1));
        if (lane == 0) {
            g_dinv[node] = dv;
            int r = g_rowloc[node] + g_boff[node / SCAN_BLK];
            g_row[node] = r;
            g_cur[node] = r;
        }
        g_y[node * HID + lane] = dv * acc;
    }
}

// 4) fill CSR (4 edges per thread, int4 loads)
__global__ void fill_kernel(const int* __restrict__ src,
                            const int* __restrict__ dst, int E) {
    int t = blockIdx.x * blockDim.x + threadIdx.x;
    int e = t * 4;
    if (e + 3 < E) {
        int4 d = __ldg(reinterpret_cast<const int4*>(dst) + t);
        int4 s = __ldg(reinterpret_cast<const int4*>(src) + t);
        g_col[atomicAdd(&g_cur[d.x], 1)] = s.x;
        g_col[atomicAdd(&g_cur[d.y], 1)] = s.y;
        g_col[atomicAdd(&g_cur[d.z], 1)] = s.z;
        g_col[atomicAdd(&g_cur[d.w], 1)] = s.w;
    } else {
        for (int k = e; k < E; k++)
            g_col[atomicAdd(&g_cur[dst[k]], 1)] = src[k];
    }
}

// ---------------------------------------------------------------------------
// Gather: warp-per-node, float4 per lane, 4 edge rows per LDG.128 instruction,
// 16 edges per batch with double-buffered index loads. Returns per-lane scalar
// h_pre = sum over incoming rows + self row, for channel c = lane.
__device__ __forceinline__ float gather_row(const float* __restrict__ ybuf,
                                            int node, int lane) {
    int beg = g_row[node];
    int cnt = g_deg[node];
    int g   = lane & 7;       // float4 group within row
    int sub = lane >> 3;      // which edge of the quad this lane handles

    float4 acc = make_float4(0.f, 0.f, 0.f, 0.f);

    int i = 0;
    int idx = (cnt >= 16 && lane < 16) ? __ldg(&g_col[beg + lane]) : 0;
    for (; i + 16 <= cnt; i += 16) {
        int nidx = (i + 32 <= cnt && lane < 16)
                 ? __ldg(&g_col[beg + i + 16 + lane]) : 0;
#pragma unroll
        for (int it = 0; it < 4; it++) {
            int s = __shfl_sync(0xffffffffu, idx, it * 4 + sub);
            float4 v = __ldcg(reinterpret_cast<const float4*>(ybuf + s * HID) + g);
            acc.x += v.x; acc.y += v.y; acc.z += v.z; acc.w += v.w;
        }
        idx = nidx;
    }

    int rem = cnt - i;
    if (rem > 0) {
        int tidx = (lane < rem) ? __ldg(&g_col[beg + i + lane]) : 0;
        for (int it = 0; it * 4 < rem; it++) {
            int e = it * 4 + sub;
            int s = __shfl_sync(0xffffffffu, tidx, e & 15);
            if (e < rem) {
                float4 v = __ldcg(reinterpret_cast<const float4*>(ybuf + s * HID) + g);
                acc.x += v.x; acc.y += v.y; acc.z += v.z; acc.w += v.w;
            }
        }
    }

    // reduce across the 4 edge-subgroups (lanes differing in bits 3,4)
#pragma unroll
    for (int m = 8; m <= 16; m <<= 1) {
        acc.x += __shfl_xor_sync(0xffffffffu, acc.x, m);
        acc.y += __shfl_xor_sync(0xffffffffu, acc.y, m);
        acc.z += __shfl_xor_sync(0xffffffffu, acc.z, m);
        acc.w += __shfl_xor_sync(0xffffffffu, acc.w, m);
    }

    // transpose: channel c = lane lives in component (lane&3) of group (lane>>2)
    int gsrc = lane >> 2;
    float cx = __shfl_sync(0xffffffffu, acc.x, gsrc);
    float cy = __shfl_sync(0xffffffffu, acc.y, gsrc);
    float cz = __shfl_sync(0xffffffffu, acc.z, gsrc);
    float cw = __shfl_sync(0xffffffffu, acc.w, gsrc);
    int sel = lane & 3;
    float v = (sel == 0) ? cx : (sel == 1) ? cy : (sel == 2) ? cz : cw;

    // self-loop term (coalesced 128B load)
    return v + ybuf[node * HID + lane];
}

// 5) layer-1 aggregation + relu + W2 transform: y2 = dinv*(relu(dinv*sum+b1) @ W2)
__global__ void agg1_kernel(const float* __restrict__ b1,
                            const float* __restrict__ W2, int n) {
    __shared__ float sW[HID * HID];
    for (int i = threadIdx.x; i < HID * HID; i += blockDim.x) sW[i] = W2[i];
    __syncthreads();

    int warp = threadIdx.x >> 5, lane = threadIdx.x & 31;
    int node = blockIdx.x * (blockDim.x >> 5) + warp;
    if (node >= n) return;

    float acc = gather_row(g_y, node, lane);
    float dv  = g_dinv[node];
    float h   = fmaxf(fmaf(dv, acc, b1[lane]), 0.f);

    float o = 0.f;
#pragma unroll
    for (int k = 0; k < HID; k++) {
        float hk = __shfl_sync(0xffffffffu, h, k);
        o = fmaf(hk, sW[k * HID + lane], o);
    }
    g_y2[node * HID + lane] = dv * o;
}

// 6) layer-2 aggregation + relu + MLP head. Resets g_deg (invariant).
__global__ void agg2_kernel(const float* __restrict__ b2,
                            const float* __restrict__ Wo1,
                            const float* __restrict__ bo1,
                            const float* __restrict__ Wo2,
                            const float* __restrict__ bo2,
                            float* __restrict__ out, int n) {
    __shared__ float sW[HID * 16];
    __shared__ float sW2[16];
    for (int i = threadIdx.x; i < HID * 16; i += blockDim.x) sW[i] = Wo1[i];
    if (threadIdx.x < 16) sW2[threadIdx.x] = Wo2[threadIdx.x];
    __syncthreads();

    int warp = threadIdx.x >> 5, lane = threadIdx.x & 31;
    int node = blockIdx.x * (blockDim.x >> 5) + warp;
    if (node >= n) return;

    float acc = gather_row(g_y2, node, lane);
    float dv  = g_dinv[node];
    float h   = fmaxf(fmaf(dv, acc, b2[lane]), 0.f);

    int j = lane & 15;
    float t = 0.f;
#pragma unroll
    for (int k = 0; k < HID; k++) {
        float hk = __shfl_sync(0xffffffffu, h, k);
        t = fmaf(hk, sW[k * 16 + j], t);
    }
    t += bo1[j];
    t = (t > 0.f) ? t : expm1f(t);          // elu
    float p = (lane < 16) ? t * sW2[j] : 0.f;
    p += __shfl_down_sync(0xffffffffu, p, 8);
    p += __shfl_down_sync(0xffffffffu, p, 4);
    p += __shfl_down_sync(0xffffffffu, p, 2);
    p += __shfl_down_sync(0xffffffffu, p, 1);
    if (lane == 0) {
        out[node] = p + bo2[0];
        g_deg[node] = 0;                    // restore invariant for next call
    }
}

// ---------------------------------------------------------------------------
extern "C" void kernel_launch(void* const* d_in, const int* in_sizes, int n_in,
                              void* d_out, int out_size) {
    const float* x   = (const float*)d_in[0];
    const int*   ei  = (const int*)  d_in[1];   // [2, E] row-major
    const float* W1  = (const float*)d_in[3];
    const float* b1  = (const float*)d_in[4];
    const float* W2  = (const float*)d_in[5];
    const float* b2  = (const float*)d_in[6];
    const float* Wo1 = (const float*)d_in[7];
    const float* bo1 = (const float*)d_in[8];
    const float* Wo2 = (const float*)d_in[9];
    const float* bo2 = (const float*)d_in[10];
    float* out = (float*)d_out;

    int n = in_sizes[0] / IN_DIM;
    int E = in_sizes[1] / 2;
    const int* src = ei;
    const int* dst = ei + E;

    const int TPB = 256;
    int node_grid = (n + (TPB / 32) - 1) / (TPB / 32);          // warp per node
    int quad_grid = (n + (TPB / 32) * 4 - 1) / ((TPB / 32) * 4); // 4 nodes/warp
    int nblk = (n + SCAN_BLK - 1) / SCAN_BLK;
    int e4_grid = ((E + 3) / 4 + TPB - 1) / TPB;

    degree_kernel<<<e4_grid, TPB>>>(dst, E);
    scan1_kernel<<<nblk, SCAN_BLK>>>(n);
    scan2_kernel<<<1, 1024>>>(nblk);
    y1_kernel<<<quad_grid, TPB>>>(x, W1, n);
    fill_kernel<<<e4_grid, TPB>>>(src, dst, E);
    agg1_kernel<<<node_grid, TPB>>>(b1, W2, n);
    agg2_kernel<<<node_grid, TPB>>>(b2, Wo1, bo1, Wo2, bo2, out, n);
}